// round 2
// baseline (speedup 1.0000x reference)
#include <cuda_runtime.h>
#include <math.h>

// ---------------- scratch (static device allocations) ----------------
__device__ double g_band[8 * 1024 * 65];   // banded ATA / L, [b][col][d]
__device__ double g_atb[8 * 1024];         // rhs / y
__device__ float  g_t[2 * 2 * 64 * 1024];  // conv1 outputs [branch][n][c][px]
__device__ float  g_att[2 * 24 * 1024];    // sigmoid(conv2 att)
__device__ float  g_grad[2 * 24 * 1024];   // conv2 grad
__device__ float  g_se[2 * 4];
__device__ float  g_sol[8 * 1024];
__device__ float  g_ygn[2 * 4 * 1024];

// ---------------- conv1: 64->64 3x3, lrelu, both branches ----------------
__global__ void __launch_bounds__(256) k_conv1(
    const float* __restrict__ x,
    const float* __restrict__ gw1, const float* __restrict__ gb1,
    const float* __restrict__ aw1, const float* __restrict__ ab1)
{
    int plane  = blockIdx.x;           // 0..255
    int branch = plane >> 7;           // 0=grad, 1=att
    int n      = (plane >> 6) & 1;
    int co     = plane & 63;
    const float* wgt  = (branch ? aw1 : gw1) + co * 576;
    float bias        = (branch ? ab1 : gb1)[co];

    __shared__ float xs[34 * 34];
    int row  = threadIdx.x >> 3;        // 0..31
    int col0 = (threadIdx.x & 7) << 2;  // 0..28 step 4

    float a0 = bias, a1 = bias, a2 = bias, a3 = bias;
    const float* xbase = x + n * 64 * 1024;

    for (int ci = 0; ci < 64; ci++) {
        __syncthreads();
        const float* xp = xbase + ci * 1024;
        for (int idx = threadIdx.x; idx < 1156; idx += 256) {
            int r = idx / 34, c = idx - r * 34;
            int gr = r - 1, gc = c - 1;
            xs[idx] = ((unsigned)gr < 32u && (unsigned)gc < 32u) ? xp[gr * 32 + gc] : 0.f;
        }
        __syncthreads();
        float w[9];
#pragma unroll
        for (int k = 0; k < 9; k++) w[k] = __ldg(wgt + ci * 9 + k);
        float s[3][6];
#pragma unroll
        for (int dy = 0; dy < 3; dy++)
#pragma unroll
            for (int dx = 0; dx < 6; dx++)
                s[dy][dx] = xs[(row + dy) * 34 + col0 + dx];
#pragma unroll
        for (int dy = 0; dy < 3; dy++) {
            float w0 = w[dy * 3], w1 = w[dy * 3 + 1], w2 = w[dy * 3 + 2];
            a0 += w0 * s[dy][0] + w1 * s[dy][1] + w2 * s[dy][2];
            a1 += w0 * s[dy][1] + w1 * s[dy][2] + w2 * s[dy][3];
            a2 += w0 * s[dy][2] + w1 * s[dy][3] + w2 * s[dy][4];
            a3 += w0 * s[dy][3] + w1 * s[dy][4] + w2 * s[dy][5];
        }
    }
    float* out = g_t + (((branch * 2 + n) * 64 + co) * 1024) + row * 32 + col0;
    out[0] = a0 > 0.f ? a0 : 0.01f * a0;
    out[1] = a1 > 0.f ? a1 : 0.01f * a1;
    out[2] = a2 > 0.f ? a2 : 0.01f * a2;
    out[3] = a3 > 0.f ? a3 : 0.01f * a3;
}

// ---------------- conv2: 64->24 3x3 (+sigmoid on att branch) ----------------
__global__ void __launch_bounds__(256) k_conv2(
    const float* __restrict__ gw2, const float* __restrict__ gb2,
    const float* __restrict__ aw2, const float* __restrict__ ab2)
{
    int plane  = blockIdx.x;            // 0..95
    int branch = plane / 48;
    int rem    = plane - branch * 48;
    int n      = rem / 24;
    int co     = rem - n * 24;
    const float* wgt = (branch ? aw2 : gw2) + co * 576;
    float bias       = (branch ? ab2 : gb2)[co];

    __shared__ float xs[34 * 34];
    int row  = threadIdx.x >> 3;
    int col0 = (threadIdx.x & 7) << 2;

    float a0 = bias, a1 = bias, a2 = bias, a3 = bias;
    const float* xbase = g_t + (branch * 2 + n) * 64 * 1024;

    for (int ci = 0; ci < 64; ci++) {
        __syncthreads();
        const float* xp = xbase + ci * 1024;
        for (int idx = threadIdx.x; idx < 1156; idx += 256) {
            int r = idx / 34, c = idx - r * 34;
            int gr = r - 1, gc = c - 1;
            xs[idx] = ((unsigned)gr < 32u && (unsigned)gc < 32u) ? xp[gr * 32 + gc] : 0.f;
        }
        __syncthreads();
        float w[9];
#pragma unroll
        for (int k = 0; k < 9; k++) w[k] = __ldg(wgt + ci * 9 + k);
        float s[3][6];
#pragma unroll
        for (int dy = 0; dy < 3; dy++)
#pragma unroll
            for (int dx = 0; dx < 6; dx++)
                s[dy][dx] = xs[(row + dy) * 34 + col0 + dx];
#pragma unroll
        for (int dy = 0; dy < 3; dy++) {
            float w0 = w[dy * 3], w1 = w[dy * 3 + 1], w2 = w[dy * 3 + 2];
            a0 += w0 * s[dy][0] + w1 * s[dy][1] + w2 * s[dy][2];
            a1 += w0 * s[dy][1] + w1 * s[dy][2] + w2 * s[dy][3];
            a2 += w0 * s[dy][2] + w1 * s[dy][3] + w2 * s[dy][4];
            a3 += w0 * s[dy][3] + w1 * s[dy][4] + w2 * s[dy][5];
        }
    }
    float* out = (branch ? g_att : g_grad) + ((n * 24 + co) * 1024) + row * 32 + col0;
    if (branch) {
        out[0] = 1.f / (1.f + expf(-a0));
        out[1] = 1.f / (1.f + expf(-a1));
        out[2] = 1.f / (1.f + expf(-a2));
        out[3] = 1.f / (1.f + expf(-a3));
    } else {
        out[0] = a0; out[1] = a1; out[2] = a2; out[3] = a3;
    }
}

// ---------------- SE branch ----------------
__global__ void __launch_bounds__(256) k_se(
    const float* __restrict__ x,
    const float* __restrict__ sw1, const float* __restrict__ sb1,
    const float* __restrict__ sw2, const float* __restrict__ sb2)
{
    int n = blockIdx.x, tid = threadIdx.x;
    __shared__ float red[256];
    __shared__ float pooled[64];
    __shared__ float s1[32];

    int c = tid >> 2, part = tid & 3;
    const float* xp = x + (n * 64 + c) * 1024 + part * 256;
    float s = 0.f;
    for (int i = 0; i < 256; i++) s += xp[i];
    red[tid] = s;
    __syncthreads();
    if (part == 0)
        pooled[c] = (red[tid] + red[tid + 1] + red[tid + 2] + red[tid + 3]) * (1.f / 1024.f);
    __syncthreads();
    if (tid < 32) {
        float a = sb1[tid];
        for (int j = 0; j < 64; j++) a += sw1[tid * 64 + j] * pooled[j];
        s1[tid] = a > 0.f ? a : 0.01f * a;
    }
    __syncthreads();
    if (tid < 4) {
        float a = sb2[tid];
        for (int j = 0; j < 32; j++) a += sw2[tid * 32 + j] * s1[j];
        g_se[n * 4 + tid] = 1.f / (1.f + expf(-a));
    }
}

// ---------------- zero band + atb, seed ridge ----------------
__global__ void k_zero()
{
    int idx = blockIdx.x * blockDim.x + threadIdx.x;
    const int NB = 8 * 1024 * 65;
    if (idx < NB) {
        g_band[idx] = (idx % 65 == 0) ? 1e-12 : 0.0;
    } else if (idx < NB + 8 * 1024) {
        g_atb[idx - NB] = 0.0;
    }
}

// ---------------- build banded ATA and ATB ----------------
__global__ void __launch_bounds__(256) k_build(const float* __restrict__ a)
{
    int t = blockIdx.x * blockDim.x + threadIdx.x;   // 0..8191
    int b = t >> 10;
    int i = t & 1023;
    int n = b >> 2;
    int g = b & 3;
    const int offs[7] = {0, 1, 2, 31, 32, 33, 64};

    for (int k = 0; k < 6; k++) {
        int ch = g * 6 + k;
        float attv  = g_att[(n * 24 + ch) * 1024 + i];
        float gradv = g_grad[(n * 24 + ch) * 1024 + i];
        double att2 = (double)attv * (double)attv;
        double wd   = att2 * (double)gradv;

        float v[7];
#pragma unroll
        for (int c = 0; c < 7; c++) {
            int col = i + offs[c];
            v[c] = (col < 1024) ? a[(i * 6 + k) * 1024 + col] : 0.f;
        }
        double* bandb = g_band + (size_t)b * 1024 * 65;
        double* atbb  = g_atb + b * 1024;
#pragma unroll
        for (int c1 = 0; c1 < 7; c1++) {
            if (v[c1] != 0.f) {
                atomicAdd(&atbb[i + offs[c1]], (double)v[c1] * wd);
#pragma unroll
                for (int c2 = 0; c2 <= c1; c2++) {
                    float prod = v[c1] * v[c2];
                    if (prod != 0.f) {
                        int colq = i + offs[c2];
                        int d    = offs[c1] - offs[c2];
                        atomicAdd(&bandb[colq * 65 + d], (double)prod * att2);
                    }
                }
            }
        }
    }
}

// ---------------- banded Cholesky + fused fwd sub + blocked back sub ----------------
__global__ void __launch_bounds__(256) k_solve()
{
    const int T = 256;
    int b   = blockIdx.x;
    int tid = threadIdx.x;
    double* band = g_band + (size_t)b * 1024 * 65;

    __shared__ double W[65 * 65];       // sliding column window (ring by col%65)
    __shared__ double yv[1024];
    __shared__ unsigned short PQ[2080];

    // triangle pair table: pairs (p,q), 1<=p<=q<=64, p-major
    {
        int base = 0;
        for (int p = 1; p <= 64; p++) {
            for (int q = p + tid; q <= 64; q += T)
                PQ[base + q - p] = (unsigned short)(p | (q << 8));
            base += 65 - p;
        }
    }
    // rhs
    for (int j = tid; j < 1024; j += T) yv[j] = g_atb[b * 1024 + j];
    // preload columns 0..63
    for (int idx = tid; idx < 64 * 65; idx += T) {
        int c = idx / 65, r = idx - c * 65;
        W[c * 65 + r] = band[c * 65 + r];
    }
    __syncthreads();

    for (int j = 0; j < 1024; j++) {
        int slot = j % 65;
        int in_c = j + 64;
        // phase 1: stream in column j+64; everyone computes pivot quantities
        if (in_c < 1024 && tid < 65) {
            W[(in_c % 65) * 65 + tid] = band[in_c * 65 + tid];
        }
        double d    = W[slot * 65 + 0];
        double inv  = rsqrt(d);
        double inv2 = inv * inv;
        double yj   = yv[j] * inv;
        int rmax    = min(64, 1023 - j);
        __syncthreads();
        // phase 2: scale column (write L to global), fwd-sub rhs, rank-1 update
        for (int r = tid + 1; r <= rmax; r += T) {
            double Lr = W[slot * 65 + r] * inv;
            band[j * 65 + r] = Lr;
            yv[j + r] -= Lr * yj;
        }
        if (tid == 0) {
            yv[j] = yj;
            band[j * 65 + 0] = inv;   // store INVERSE of diag for back-sub
        }
        for (int idx = tid; idx < 2080; idx += T) {
            int pq = PQ[idx];
            int p = pq & 255, q = pq >> 8;
            if (q <= rmax) {
                double Lq = W[slot * 65 + q];
                double Lp = W[slot * 65 + p];
                int ds = slot + p; if (ds >= 65) ds -= 65;
                W[ds * 65 + (q - p)] -= Lq * Lp * inv2;
            }
        }
        __syncthreads();
    }

    // ---- back substitution: L^T x = y, blocked by 64 rows ----
    double* LB = W;   // reuse: 64 rows x 65 band entries
    for (int blk = 15; blk >= 0; blk--) {
        int j0 = blk * 64;
        for (int idx = tid; idx < 64 * 65; idx += T)
            LB[idx] = band[j0 * 65 + idx];
        __syncthreads();
        // tail contributions from already-final x in later blocks
        if (tid < 64) {
            int t = tid, jj = j0 + t;
            double s = 0.0;
            for (int r = 64 - t; r <= 64; r++) {
                int jr = jj + r;
                if (jr < 1024) s += LB[t * 65 + r] * yv[jr];
            }
            yv[jj] -= s;
        }
        __syncthreads();
        // in-block serial sweep (keep yv unscaled; scale at the end)
        for (int t = 63; t >= 1; t--) {
            double xval = yv[j0 + t] * LB[t * 65];
            if (tid < t) yv[j0 + tid] -= LB[tid * 65 + (t - tid)] * xval;
            __syncthreads();
        }
        if (tid < 64) yv[j0 + tid] *= LB[tid * 65];
        __syncthreads();
    }

    for (int j = tid; j < 1024; j += T) g_sol[b * 1024 + j] = (float)yv[j];
}

// ---------------- GroupNorm(1, GR) + affine + SE scale ----------------
__global__ void __launch_bounds__(256) k_gn(const float* __restrict__ gn_g,
                                            const float* __restrict__ gn_b)
{
    int n = blockIdx.x, tid = threadIdx.x;
    __shared__ double s1[256], s2[256];
    double a = 0.0, c = 0.0;
    for (int idx = tid; idx < 4096; idx += 256) {
        double v = g_sol[n * 4096 + idx];
        a += v; c += v * v;
    }
    s1[tid] = a; s2[tid] = c;
    __syncthreads();
    for (int off = 128; off > 0; off >>= 1) {
        if (tid < off) { s1[tid] += s1[tid + off]; s2[tid] += s2[tid + off]; }
        __syncthreads();
    }
    double mu  = s1[0] * (1.0 / 4096.0);
    double var = s2[0] * (1.0 / 4096.0) - mu * mu;
    double invstd = rsqrt(var + 1e-5);
    for (int idx = tid; idx < 4096; idx += 256) {
        int g = idx >> 10;
        float v = (float)((g_sol[n * 4096 + idx] - mu) * invstd);
        v = v * gn_g[g] + gn_b[g];
        v *= g_se[n * 4 + g];
        g_ygn[n * 4096 + idx] = v;
    }
}

// ---------------- final conv: 4->128 3x3 ----------------
__global__ void __launch_bounds__(256) k_convf(
    const float* __restrict__ pw, const float* __restrict__ pb,
    float* __restrict__ out)
{
    int plane = blockIdx.x;          // 0..255
    int n  = plane >> 7;
    int co = plane & 127;
    __shared__ float ys[4 * 1156];
    for (int idx = threadIdx.x; idx < 4 * 1156; idx += 256) {
        int ci = idx / 1156, rr = idx - ci * 1156;
        int r = rr / 34, c = rr - r * 34;
        int gr = r - 1, gc = c - 1;
        ys[idx] = ((unsigned)gr < 32u && (unsigned)gc < 32u)
                  ? g_ygn[(n * 4 + ci) * 1024 + gr * 32 + gc] : 0.f;
    }
    __syncthreads();

    const float* wgt = pw + co * 36;
    float bias = pb[co];
    int row  = threadIdx.x >> 3;
    int col0 = (threadIdx.x & 7) << 2;
    float a0 = bias, a1 = bias, a2 = bias, a3 = bias;
#pragma unroll
    for (int ci = 0; ci < 4; ci++) {
        float w[9];
#pragma unroll
        for (int k = 0; k < 9; k++) w[k] = __ldg(wgt + ci * 9 + k);
        float s[3][6];
#pragma unroll
        for (int dy = 0; dy < 3; dy++)
#pragma unroll
            for (int dx = 0; dx < 6; dx++)
                s[dy][dx] = ys[ci * 1156 + (row + dy) * 34 + col0 + dx];
#pragma unroll
        for (int dy = 0; dy < 3; dy++) {
            float w0 = w[dy * 3], w1 = w[dy * 3 + 1], w2 = w[dy * 3 + 2];
            a0 += w0 * s[dy][0] + w1 * s[dy][1] + w2 * s[dy][2];
            a1 += w0 * s[dy][1] + w1 * s[dy][2] + w2 * s[dy][3];
            a2 += w0 * s[dy][2] + w1 * s[dy][3] + w2 * s[dy][4];
            a3 += w0 * s[dy][3] + w1 * s[dy][4] + w2 * s[dy][5];
        }
    }
    float* o = out + ((n * 128 + co) * 1024) + row * 32 + col0;
    o[0] = a0; o[1] = a1; o[2] = a2; o[3] = a3;
}

// ---------------- launcher ----------------
extern "C" void kernel_launch(void* const* d_in, const int* in_sizes, int n_in,
                              void* d_out, int out_size)
{
    const float* x    = (const float*)d_in[0];
    const float* a    = (const float*)d_in[1];
    const float* gw1  = (const float*)d_in[2];
    const float* gb1  = (const float*)d_in[3];
    const float* gw2  = (const float*)d_in[4];
    const float* gb2  = (const float*)d_in[5];
    const float* aw1  = (const float*)d_in[6];
    const float* ab1  = (const float*)d_in[7];
    const float* aw2  = (const float*)d_in[8];
    const float* ab2  = (const float*)d_in[9];
    const float* sw1  = (const float*)d_in[10];
    const float* sb1  = (const float*)d_in[11];
    const float* sw2  = (const float*)d_in[12];
    const float* sb2  = (const float*)d_in[13];
    const float* gn_g = (const float*)d_in[14];
    const float* gn_b = (const float*)d_in[15];
    const float* pw   = (const float*)d_in[16];
    const float* pb   = (const float*)d_in[17];
    float* out = (float*)d_out;

    k_conv1<<<256, 256>>>(x, gw1, gb1, aw1, ab1);
    k_conv2<<<96, 256>>>(gw2, gb2, aw2, ab2);
    k_se<<<2, 256>>>(x, sw1, sb1, sw2, sb2);
    {
        int total = 8 * 1024 * 65 + 8 * 1024;
        k_zero<<<(total + 511) / 512, 512>>>();
    }
    k_build<<<32, 256>>>(a);
    k_solve<<<8, 256>>>();
    k_gn<<<2, 256>>>(gn_g, gn_b);
    k_convf<<<256, 256>>>(pw, pb, out);
}